// round 12
// baseline (speedup 1.0000x reference)
#include <cuda_runtime.h>
#include <cuda_fp16.h>
#include <mma.h>
#include <cstdint>

using namespace nvcuda;

// Problem constants
#define NROWS 100000
#define DIN   1024
#define DD    512
#define NG    8
#define GS    12500

// GEMM tiling (round-6 proven config)
#define BM 128
#define BN 128
#define BK 16
#define NTHREADS 256
#define STAGES 4
#define LDA 24       // As stride in halfs (48B)
#define LDB 136      // Bs stride in halfs (272B)
#define LDCS 68      // epilogue staging stride (fp32)
#define A_BYTES (BM * LDA * 2)            // 6144
#define B_BYTES (BK * LDB * 2)            // 4352
#define BUFB (A_BYTES + B_BYTES)          // 10496
#define SMEM_BYTES (STAGES * BUFB)        // 41984 (< 48KB default)
#define MTILES ((NROWS + BM - 1) / BM)    // 782
#define NSLICES (DD / BN)                 // 4

// ---------------- scratch (device globals; no allocation allowed) ----------
__device__ __half g_xh[(size_t)NROWS * DIN];   // 200 MB
__device__ __half g_th[(size_t)NROWS * DD];    // 100 MB (tmid, fp16)
__device__ __half g_W1h[DIN * DD];
__device__ __half g_Vh[DD * DD];
__device__ float    g_escore[NROWS];           // exp(scores)
__device__ float    g_d[NROWS];
__device__ float    g_spart[NSLICES * NROWS];
__device__ float    g_dpart[NSLICES * NROWS];
__device__ float    g_tAA[NG * GS];
__device__ float    g_bag[NG * DD];
__device__ float    g_Z;
__device__ int      g_imax[NG];
__device__ int      g_imin[NG];

// ---------------- helpers ---------------------------------------------------
__device__ __forceinline__ float tanh_fast(float x) {
    float y;
    asm("tanh.approx.f32 %0, %1;" : "=f"(y) : "f"(x));
    return y;
}
__device__ __forceinline__ void cp_async16(uint32_t dst, const void* src, bool pred) {
    int sz = pred ? 16 : 0;
    asm volatile("cp.async.cg.shared.global [%0], [%1], 16, %2;\n"
                 :: "r"(dst), "l"(src), "r"(sz));
}
__device__ __forceinline__ void cp_commit() {
    asm volatile("cp.async.commit_group;\n" ::: "memory");
}
template <int N>
__device__ __forceinline__ void cp_wait() {
    asm volatile("cp.async.wait_group %0;\n" :: "n"(N) : "memory");
}

// ---------------- prep: convert x, W1, V to fp16 ----------------------------
__global__ void prep_kernel(const float* __restrict__ x, const float* __restrict__ W1,
                            const float* __restrict__ V) {
    int t = blockIdx.x * blockDim.x + threadIdx.x;
    int stride = gridDim.x * blockDim.x;
    // x: streaming stores (consumed exactly 4x later, 200MB — keep L2 clean)
    for (int i = t; i < NROWS * DIN / 4; i += stride) {
        float4 v = __ldg(&((const float4*)x)[i]);
        __half h[4] = {__float2half(v.x), __float2half(v.y),
                       __float2half(v.z), __float2half(v.w)};
        __stcs(&((uint2*)g_xh)[i], *(uint2*)h);
    }
    for (int i = t; i < DIN * DD / 4; i += stride) {
        float4 v = ((const float4*)W1)[i];
        __half h[4] = {__float2half(v.x), __float2half(v.y),
                       __float2half(v.z), __float2half(v.w)};
        ((uint2*)g_W1h)[i] = *(uint2*)h;
    }
    for (int i = t; i < DD * DD / 4; i += stride) {
        float4 v = ((const float4*)V)[i];
        __half h[4] = {__float2half(v.x), __float2half(v.y),
                       __float2half(v.z), __float2half(v.w)};
        ((uint2*)g_Vh)[i] = *(uint2*)h;
    }
    if (t < NG * DD) g_bag[t] = 0.f;
    if (t == 0) g_Z = 0.f;
}

// ---------------- fp16 WMMA GEMM, cp.async 4-stage pipeline (round-6) -------
// MODE 0: C = x @ W1 (K=1024); epilogue: relu -> g_th (fp16), dpart = relu(C).(Wc1-Wc0)
// MODE 1: C = tmid @ V (K=512); epilogue: spart = sum_n tanh(C[.,n]) * watt[n]
template <int KTOT, int MODE>
__global__ void __launch_bounds__(NTHREADS, 2)
gemm_mma(const float* __restrict__ watt, const float* __restrict__ Wc) {
    extern __shared__ char dsm[];
    const __half* Ag = (MODE == 0) ? g_xh : g_th;
    const __half* Bg = (MODE == 0) ? g_W1h : g_Vh;

    const int tid = threadIdx.x;
    const int wid = tid >> 5;
    const int m0 = blockIdx.x * BM;
    const int n0 = blockIdx.y * BN;

    const int wm = (wid >> 1) * 32;
    const int wn = (wid & 1) * 64;

    wmma::fragment<wmma::accumulator, 16, 16, 16, float> acc[2][4];
#pragma unroll
    for (int i = 0; i < 2; i++)
#pragma unroll
        for (int n = 0; n < 4; n++) wmma::fill_fragment(acc[i][n], 0.f);

    const int arow = tid >> 1, ach = tid & 1;
    const int brow = tid >> 4, bch = tid & 15;
    const bool aval = (m0 + arow) < NROWS;
    const int arowc = aval ? (m0 + arow) : (NROWS - 1);
    const uint32_t sb0 = (uint32_t)__cvta_generic_to_shared(dsm);

    auto issue = [&](int kcs) {
        const uint32_t sb = sb0 + (kcs % STAGES) * BUFB;
        const __half* ga = Ag + (size_t)arowc * KTOT + kcs * BK + ach * 8;
        cp_async16(sb + arow * 48 + ach * 16, ga, aval);
        size_t gb = (size_t)(kcs * BK + brow) * DD + n0 + bch * 8;
        cp_async16(sb + A_BYTES + brow * 272 + bch * 16, Bg + gb, true);
        cp_commit();
    };

    const int KC = KTOT / BK;
#pragma unroll
    for (int s = 0; s < STAGES - 1; s++) issue(s);

    for (int kc = 0; kc < KC; kc++) {
        cp_wait<STAGES - 2>();
        __syncthreads();
        if (kc + STAGES - 1 < KC) issue(kc + STAGES - 1);

        char* buf = dsm + (kc % STAGES) * BUFB;
        __half* As = (__half*)buf;
        __half* Bs = (__half*)(buf + A_BYTES);

        wmma::fragment<wmma::matrix_a, 16, 16, 16, __half, wmma::row_major> fa[2];
#pragma unroll
        for (int i = 0; i < 2; i++)
            wmma::load_matrix_sync(fa[i], &As[(wm + 16 * i) * LDA], LDA);
#pragma unroll
        for (int n = 0; n < 4; n++) {
            wmma::fragment<wmma::matrix_b, 16, 16, 16, __half, wmma::row_major> fb;
            wmma::load_matrix_sync(fb, &Bs[wn + 16 * n], LDB);
#pragma unroll
            for (int i = 0; i < 2; i++)
                wmma::mma_sync(acc[i][n], fa[i], fb, acc[i][n]);
        }
        __syncthreads();
    }
    cp_wait<0>();
    __syncthreads();

    // ---------------- epilogue: stage C in two 64-col halves ----------------
    float* Cs = (float*)dsm;
    const int row = tid >> 1;
    const int q = tid & 1;
    const int grow = m0 + row;
    float racc = 0.f;

#pragma unroll
    for (int hn = 0; hn < 2; hn++) {
        __syncthreads();
        if ((wid & 1) == hn) {
#pragma unroll
            for (int i = 0; i < 2; i++)
#pragma unroll
                for (int n = 0; n < 4; n++)
                    wmma::store_matrix_sync(&Cs[(wm + 16 * i) * LDCS + 16 * n],
                                            acc[i][n], LDCS, wmma::mem_row_major);
        }
        __syncthreads();
        if (grow < NROWS) {
            const int cbase = n0 + hn * 64 + q * 32;
            if (MODE == 0) {
#pragma unroll
                for (int j = 0; j < 32; j += 4) {
                    float4 v = *(float4*)&Cs[row * LDCS + q * 32 + j];
                    float vv[4] = {fmaxf(v.x, 0.f), fmaxf(v.y, 0.f),
                                   fmaxf(v.z, 0.f), fmaxf(v.w, 0.f)};
                    __half h[4];
                    int c = cbase + j;
#pragma unroll
                    for (int e = 0; e < 4; e++) {
                        h[e] = __float2half(vv[e]);
                        racc = fmaf(vv[e], Wc[2 * (c + e) + 1] - Wc[2 * (c + e)], racc);
                    }
                    *(uint2*)&g_th[(size_t)grow * DD + c] = *(uint2*)h;
                }
            } else {
#pragma unroll
                for (int j = 0; j < 32; j++) {
                    float y = Cs[row * LDCS + q * 32 + j];
                    racc = fmaf(tanh_fast(y), watt[cbase + j], racc);
                }
            }
        }
    }
    racc += __shfl_xor_sync(0xFFFFFFFFu, racc, 1);
    if (q == 0 && grow < NROWS) {
        if (MODE == 0)
            g_dpart[(size_t)blockIdx.y * NROWS + grow] = racc;
        else
            g_spart[(size_t)blockIdx.y * NROWS + grow] = racc;
    }
}

// ---------------- combine partials + exp + global Z --------------------------
// scores are bounded (|s| <= sum|w_att| ~ 8) so exp needs no max shift.
__global__ void combine_kernel() {
    __shared__ float sm[256];
    int i = blockIdx.x * blockDim.x + threadIdx.x;
    float e = 0.f;
    if (i < NROWS) {
        g_d[i] = (g_dpart[i] + g_dpart[NROWS + i]) +
                 (g_dpart[2 * NROWS + i] + g_dpart[3 * NROWS + i]);
        float s = (g_spart[i] + g_spart[NROWS + i]) +
                  (g_spart[2 * NROWS + i] + g_spart[3 * NROWS + i]);
        e = expf(s);
        g_escore[i] = e;
    }
    sm[threadIdx.x] = e;
    __syncthreads();
    for (int o = 128; o > 0; o >>= 1) {
        if (threadIdx.x < o) sm[threadIdx.x] += sm[threadIdx.x + o];
        __syncthreads();
    }
    if (threadIdx.x == 0) atomicAdd(&g_Z, sm[0]);
}

// ---------------- per-group re-softmax + argmax/argmin ----------------------
// AA values are in (0,1) so the group softmax also needs no max shift.
#define GITER 13  // ceil(12500/1024)
__global__ __launch_bounds__(1024, 1)
void group_kernel(const int* __restrict__ idx) {
    __shared__ float sv[1024];
    __shared__ int si[1024];
    const int g = blockIdx.x;
    const int tid = threadIdx.x;
    const float invZ = 1.f / g_Z;

    float ex[GITER];
    int js[GITER];
    float lsum = 0.f;
#pragma unroll
    for (int t = 0; t < GITER; t++) {
        int i = tid + t * 1024;
        if (i < GS) {
            int j = idx[g * GS + i];
            float a = g_escore[j] * invZ;   // AA[j] in (0,1)
            ex[t] = expf(a);
            js[t] = j;
            lsum += ex[t];
        } else {
            ex[t] = 0.f;
            js[t] = 0;
        }
    }
    sv[tid] = lsum;
    __syncthreads();
    for (int s = 512; s > 0; s >>= 1) {
        if (tid < s) sv[tid] += sv[tid + s];
        __syncthreads();
    }
    const float invS = 1.f / sv[0];
    __syncthreads();

    float bq = -1e30f; int bi = GS;
    float wq =  1e30f; int wi = GS;
#pragma unroll
    for (int t = 0; t < GITER; t++) {
        int i = tid + t * 1024;
        if (i < GS) {
            float ta = ex[t] * invS;
            g_tAA[g * GS + i] = ta;
            float qv = ta * g_d[js[t]];
            if (qv > bq || (qv == bq && i < bi)) { bq = qv; bi = i; }
            if (qv < wq || (qv == wq && i < wi)) { wq = qv; wi = i; }
        }
    }
    sv[tid] = bq; si[tid] = bi;
    __syncthreads();
    for (int s = 512; s > 0; s >>= 1) {
        if (tid < s) {
            float v2 = sv[tid + s]; int i2 = si[tid + s];
            if (v2 > sv[tid] || (v2 == sv[tid] && i2 < si[tid])) { sv[tid] = v2; si[tid] = i2; }
        }
        __syncthreads();
    }
    if (tid == 0) g_imax[g] = si[0];
    __syncthreads();
    sv[tid] = wq; si[tid] = wi;
    __syncthreads();
    for (int s = 512; s > 0; s >>= 1) {
        if (tid < s) {
            float v2 = sv[tid + s]; int i2 = si[tid + s];
            if (v2 < sv[tid] || (v2 == sv[tid] && i2 < si[tid])) { sv[tid] = v2; si[tid] = i2; }
        }
        __syncthreads();
    }
    if (tid == 0) g_imin[g] = si[0];
}

// ---------------- bag = sum_i tAA_i * tmid[idx_i] ---------------------------
#define BPG 64
__global__ void bag_kernel(const int* __restrict__ idx) {
    const int g = blockIdx.y;
    const int blk = blockIdx.x;
    const int tid = threadIdx.x;  // 256
    const int CH = (GS + BPG - 1) / BPG;
    int i0 = blk * CH;
    int i1 = i0 + CH; if (i1 > GS) i1 = GS;
    float a0 = 0.f, a1 = 0.f;
    for (int i = i0; i < i1; i++) {
        int j = idx[g * GS + i];
        float w = g_tAA[g * GS + i];
        size_t base = (size_t)j * DD;
        a0 = fmaf(w, __half2float(g_th[base + tid]), a0);
        a1 = fmaf(w, __half2float(g_th[base + tid + 256]), a1);
    }
    atomicAdd(&g_bag[g * DD + tid], a0);
    atomicAdd(&g_bag[g * DD + tid + 256], a1);
}

// ---------------- final: preds + pseudo feats --------------------------------
__global__ void final_kernel(const float* __restrict__ Wc, const float* __restrict__ bc,
                             float* __restrict__ out) {
    const int tid = threadIdx.x;  // 512
    const int w = tid >> 5, lane = tid & 31;
    if (w < 16) {
        int g = w >> 1, c = w & 1;
        float s = 0.f;
        for (int k = lane; k < DD; k += 32)
            s = fmaf(g_bag[g * DD + k], Wc[k * 2 + c], s);
#pragma unroll
        for (int o = 16; o > 0; o >>= 1) s += __shfl_down_sync(0xFFFFFFFFu, s, o);
        if (lane == 0) out[g * 2 + c] = s + bc[c];
    }
    for (int e = tid; e < NG * 2 * DD; e += 512) {
        int g = e / (2 * DD);
        int r = (e / DD) & 1;
        int c = e % DD;
        int rowi = r ? g_imin[g] : g_imax[g];
        out[16 + e] = __half2float(g_th[(size_t)rowi * DD + c]);
    }
}

// ---------------- launch ------------------------------------------------------
extern "C" void kernel_launch(void* const* d_in, const int* in_sizes, int n_in,
                              void* d_out, int out_size) {
    const float* x    = (const float*)d_in[0];
    const int*   idx  = (const int*)d_in[1];
    const float* W1   = (const float*)d_in[2];
    const float* V    = (const float*)d_in[3];
    const float* watt = (const float*)d_in[4];
    const float* Wc   = (const float*)d_in[5];
    const float* bc   = (const float*)d_in[6];
    float* out = (float*)d_out;

    prep_kernel<<<4096, 256>>>(x, W1, V);
    gemm_mma<DIN, 0><<<dim3(MTILES, NSLICES), NTHREADS, SMEM_BYTES>>>(watt, Wc);
    gemm_mma<DD, 1><<<dim3(MTILES, NSLICES), NTHREADS, SMEM_BYTES>>>(watt, Wc);
    combine_kernel<<<(NROWS + 255) / 256, 256>>>();
    group_kernel<<<NG, 1024>>>(idx);
    bag_kernel<<<dim3(BPG, NG), 256>>>(idx);
    final_kernel<<<1, 512>>>(Wc, bc, out);
}

// round 13
// speedup vs baseline: 1.0510x; 1.0510x over previous
#include <cuda_runtime.h>
#include <cuda_fp16.h>
#include <mma.h>
#include <cstdint>

using namespace nvcuda;

// Problem constants
#define NROWS 100000
#define DIN   1024
#define DD    512
#define NG    8
#define GS    12500

// GEMM tiling: BK=32, 3-stage cp.async ring
#define BM 128
#define BN 128
#define BK 32
#define NTHREADS 256
#define STAGES 3
#define LDA 40       // A stride in halfs (80B): 32 data + 8 pad, ldsm conflict-free
#define LDB 136      // B stride in halfs (272B): 128 data + 8 pad
#define LDCS 68      // epilogue staging stride (fp32)
#define A_BYTES (BM * LDA * 2)            // 10240
#define B_BYTES (BK * LDB * 2)            // 8704
#define BUFB (A_BYTES + B_BYTES)          // 18944
#define SMEM_BYTES (STAGES * BUFB)        // 56832 (needs attr, 2 CTA/SM ok)
#define MTILES ((NROWS + BM - 1) / BM)    // 782
#define NSLICES (DD / BN)                 // 4

// ---------------- scratch (device globals; no allocation allowed) ----------
__device__ __half g_xh[(size_t)NROWS * DIN];   // 200 MB
__device__ __half g_th[(size_t)NROWS * DD];    // 100 MB (tmid, fp16)
__device__ __half g_W1h[DIN * DD];
__device__ __half g_Vh[DD * DD];
__device__ float    g_escore[NROWS];           // exp(scores)
__device__ float    g_d[NROWS];
__device__ float    g_spart[NSLICES * NROWS];
__device__ float    g_dpart[NSLICES * NROWS];
__device__ float    g_tAA[NG * GS];
__device__ float    g_bag[NG * DD];
__device__ float    g_Z;
__device__ int      g_imax[NG];
__device__ int      g_imin[NG];

// ---------------- helpers ---------------------------------------------------
__device__ __forceinline__ float tanh_fast(float x) {
    float y;
    asm("tanh.approx.f32 %0, %1;" : "=f"(y) : "f"(x));
    return y;
}
__device__ __forceinline__ void cp_async16(uint32_t dst, const void* src, bool pred) {
    int sz = pred ? 16 : 0;
    asm volatile("cp.async.cg.shared.global [%0], [%1], 16, %2;\n"
                 :: "r"(dst), "l"(src), "r"(sz));
}
__device__ __forceinline__ void cp_commit() {
    asm volatile("cp.async.commit_group;\n" ::: "memory");
}
template <int N>
__device__ __forceinline__ void cp_wait() {
    asm volatile("cp.async.wait_group %0;\n" :: "n"(N) : "memory");
}

// ---------------- prep: convert x, W1, V to fp16 (round-6 exact) ------------
__global__ void prep_kernel(const float* __restrict__ x, const float* __restrict__ W1,
                            const float* __restrict__ V) {
    int t = blockIdx.x * blockDim.x + threadIdx.x;
    int stride = gridDim.x * blockDim.x;
    for (int i = t; i < NROWS * DIN / 4; i += stride) {
        float4 v = ((const float4*)x)[i];
        __half h[4] = {__float2half(v.x), __float2half(v.y),
                       __float2half(v.z), __float2half(v.w)};
        ((uint2*)g_xh)[i] = *(uint2*)h;
    }
    for (int i = t; i < DIN * DD / 4; i += stride) {
        float4 v = ((const float4*)W1)[i];
        __half h[4] = {__float2half(v.x), __float2half(v.y),
                       __float2half(v.z), __float2half(v.w)};
        ((uint2*)g_W1h)[i] = *(uint2*)h;
    }
    for (int i = t; i < DD * DD / 4; i += stride) {
        float4 v = ((const float4*)V)[i];
        __half h[4] = {__float2half(v.x), __float2half(v.y),
                       __float2half(v.z), __float2half(v.w)};
        ((uint2*)g_Vh)[i] = *(uint2*)h;
    }
    if (t < NG * DD) g_bag[t] = 0.f;
    if (t == 0) g_Z = 0.f;
}

// ---------------- fp16 WMMA GEMM, BK=32, 3-stage cp.async -------------------
// MODE 0: C = x @ W1 (K=1024); epilogue: relu -> g_th (fp16), dpart = relu(C).(Wc1-Wc0)
// MODE 1: C = tmid @ V (K=512); epilogue: spart = sum_n tanh(C[.,n]) * watt[n]
template <int KTOT, int MODE>
__global__ void __launch_bounds__(NTHREADS, 2)
gemm_mma(const float* __restrict__ watt, const float* __restrict__ Wc) {
    extern __shared__ char dsm[];
    const __half* Ag = (MODE == 0) ? g_xh : g_th;
    const __half* Bg = (MODE == 0) ? g_W1h : g_Vh;

    const int tid = threadIdx.x;
    const int wid = tid >> 5;
    const int m0 = blockIdx.x * BM;
    const int n0 = blockIdx.y * BN;

    const int wm = (wid >> 1) * 32;
    const int wn = (wid & 1) * 64;

    wmma::fragment<wmma::accumulator, 16, 16, 16, float> acc[2][4];
#pragma unroll
    for (int i = 0; i < 2; i++)
#pragma unroll
        for (int n = 0; n < 4; n++) wmma::fill_fragment(acc[i][n], 0.f);

    // cp.async maps: A tile 128x32 halfs = 512 x 16B chunks; 2 per thread.
    //   chunk ch: row = ch>>2, kq = ch&3 -> dst row*80 + kq*16
    // B tile 32x128 halfs = 512 x 16B chunks; 2 per thread.
    //   chunk ch: row = ch>>4, col = ch&15 -> dst row*272 + col*16
    const int a_r0 = tid >> 2,        a_k0 = tid & 3;
    const int a_r1 = (tid + 256) >> 2, a_k1 = tid & 3;
    const bool av0 = (m0 + a_r0) < NROWS;
    const bool av1 = (m0 + a_r1) < NROWS;
    const int ag0 = av0 ? (m0 + a_r0) : (NROWS - 1);
    const int ag1 = av1 ? (m0 + a_r1) : (NROWS - 1);
    const int b_r0 = tid >> 4,        b_c0 = tid & 15;
    const int b_r1 = (tid + 256) >> 4, b_c1 = tid & 15;
    const uint32_t sb0 = (uint32_t)__cvta_generic_to_shared(dsm);

    auto issue = [&](int kcs) {
        const uint32_t sb = sb0 + (kcs % STAGES) * BUFB;
        cp_async16(sb + a_r0 * 80 + a_k0 * 16,
                   Ag + (size_t)ag0 * KTOT + kcs * BK + a_k0 * 8, av0);
        cp_async16(sb + a_r1 * 80 + a_k1 * 16,
                   Ag + (size_t)ag1 * KTOT + kcs * BK + a_k1 * 8, av1);
        cp_async16(sb + A_BYTES + b_r0 * 272 + b_c0 * 16,
                   Bg + (size_t)(kcs * BK + b_r0) * DD + n0 + b_c0 * 8, true);
        cp_async16(sb + A_BYTES + b_r1 * 272 + b_c1 * 16,
                   Bg + (size_t)(kcs * BK + b_r1) * DD + n0 + b_c1 * 8, true);
        cp_commit();
    };

    const int KC = KTOT / BK;   // 32 (MODE 0) / 16 (MODE 1)
#pragma unroll
    for (int s = 0; s < STAGES - 1; s++) issue(s);

    for (int kc = 0; kc < KC; kc++) {
        cp_wait<STAGES - 2>();
        __syncthreads();
        if (kc + STAGES - 1 < KC) issue(kc + STAGES - 1);

        char* buf = dsm + (kc % STAGES) * BUFB;
        __half* As = (__half*)buf;
        __half* Bs = (__half*)(buf + A_BYTES);

#pragma unroll
        for (int ks = 0; ks < 2; ks++) {
            wmma::fragment<wmma::matrix_a, 16, 16, 16, __half, wmma::row_major> fa[2];
#pragma unroll
            for (int i = 0; i < 2; i++)
                wmma::load_matrix_sync(fa[i], &As[(wm + 16 * i) * LDA + ks * 16], LDA);
#pragma unroll
            for (int n = 0; n < 4; n++) {
                wmma::fragment<wmma::matrix_b, 16, 16, 16, __half, wmma::row_major> fb;
                wmma::load_matrix_sync(fb, &Bs[ks * 16 * LDB + wn + 16 * n], LDB);
#pragma unroll
                for (int i = 0; i < 2; i++)
                    wmma::mma_sync(acc[i][n], fa[i], fb, acc[i][n]);
            }
        }
        __syncthreads();
    }
    cp_wait<0>();
    __syncthreads();

    // ---------------- epilogue: stage C in two 64-col halves ----------------
    float* Cs = (float*)dsm;   // 34816 B < SMEM_BYTES
    const int row = tid >> 1;
    const int q = tid & 1;
    const int grow = m0 + row;
    float racc = 0.f;

#pragma unroll
    for (int hn = 0; hn < 2; hn++) {
        __syncthreads();
        if ((wid & 1) == hn) {
#pragma unroll
            for (int i = 0; i < 2; i++)
#pragma unroll
                for (int n = 0; n < 4; n++)
                    wmma::store_matrix_sync(&Cs[(wm + 16 * i) * LDCS + 16 * n],
                                            acc[i][n], LDCS, wmma::mem_row_major);
        }
        __syncthreads();
        if (grow < NROWS) {
            const int cbase = n0 + hn * 64 + q * 32;
            if (MODE == 0) {
#pragma unroll
                for (int j = 0; j < 32; j += 4) {
                    float4 v = *(float4*)&Cs[row * LDCS + q * 32 + j];
                    float vv[4] = {fmaxf(v.x, 0.f), fmaxf(v.y, 0.f),
                                   fmaxf(v.z, 0.f), fmaxf(v.w, 0.f)};
                    __half h[4];
                    int c = cbase + j;
#pragma unroll
                    for (int e = 0; e < 4; e++) {
                        h[e] = __float2half(vv[e]);
                        racc = fmaf(vv[e], Wc[2 * (c + e) + 1] - Wc[2 * (c + e)], racc);
                    }
                    *(uint2*)&g_th[(size_t)grow * DD + c] = *(uint2*)h;
                }
            } else {
#pragma unroll
                for (int j = 0; j < 32; j++) {
                    float y = Cs[row * LDCS + q * 32 + j];
                    racc = fmaf(tanh_fast(y), watt[cbase + j], racc);
                }
            }
        }
    }
    racc += __shfl_xor_sync(0xFFFFFFFFu, racc, 1);
    if (q == 0 && grow < NROWS) {
        if (MODE == 0)
            g_dpart[(size_t)blockIdx.y * NROWS + grow] = racc;
        else
            g_spart[(size_t)blockIdx.y * NROWS + grow] = racc;
    }
}

// ---------------- combine partials + exp + global Z --------------------------
__global__ void combine_kernel() {
    __shared__ float sm[256];
    int i = blockIdx.x * blockDim.x + threadIdx.x;
    float e = 0.f;
    if (i < NROWS) {
        g_d[i] = (g_dpart[i] + g_dpart[NROWS + i]) +
                 (g_dpart[2 * NROWS + i] + g_dpart[3 * NROWS + i]);
        float s = (g_spart[i] + g_spart[NROWS + i]) +
                  (g_spart[2 * NROWS + i] + g_spart[3 * NROWS + i]);
        e = expf(s);
        g_escore[i] = e;
    }
    sm[threadIdx.x] = e;
    __syncthreads();
    for (int o = 128; o > 0; o >>= 1) {
        if (threadIdx.x < o) sm[threadIdx.x] += sm[threadIdx.x + o];
        __syncthreads();
    }
    if (threadIdx.x == 0) atomicAdd(&g_Z, sm[0]);
}

// ---------------- per-group re-softmax + argmax/argmin ----------------------
#define GITER 13  // ceil(12500/1024)
__global__ __launch_bounds__(1024, 1)
void group_kernel(const int* __restrict__ idx) {
    __shared__ float sv[1024];
    __shared__ int si[1024];
    const int g = blockIdx.x;
    const int tid = threadIdx.x;
    const float invZ = 1.f / g_Z;

    float ex[GITER];
    int js[GITER];
    float lsum = 0.f;
#pragma unroll
    for (int t = 0; t < GITER; t++) {
        int i = tid + t * 1024;
        if (i < GS) {
            int j = idx[g * GS + i];
            float a = g_escore[j] * invZ;   // AA[j] in (0,1)
            ex[t] = expf(a);
            js[t] = j;
            lsum += ex[t];
        } else {
            ex[t] = 0.f;
            js[t] = 0;
        }
    }
    sv[tid] = lsum;
    __syncthreads();
    for (int s = 512; s > 0; s >>= 1) {
        if (tid < s) sv[tid] += sv[tid + s];
        __syncthreads();
    }
    const float invS = 1.f / sv[0];
    __syncthreads();

    float bq = -1e30f; int bi = GS;
    float wq =  1e30f; int wi = GS;
#pragma unroll
    for (int t = 0; t < GITER; t++) {
        int i = tid + t * 1024;
        if (i < GS) {
            float ta = ex[t] * invS;
            g_tAA[g * GS + i] = ta;
            float qv = ta * g_d[js[t]];
            if (qv > bq || (qv == bq && i < bi)) { bq = qv; bi = i; }
            if (qv < wq || (qv == wq && i < wi)) { wq = qv; wi = i; }
        }
    }
    sv[tid] = bq; si[tid] = bi;
    __syncthreads();
    for (int s = 512; s > 0; s >>= 1) {
        if (tid < s) {
            float v2 = sv[tid + s]; int i2 = si[tid + s];
            if (v2 > sv[tid] || (v2 == sv[tid] && i2 < si[tid])) { sv[tid] = v2; si[tid] = i2; }
        }
        __syncthreads();
    }
    if (tid == 0) g_imax[g] = si[0];
    __syncthreads();
    sv[tid] = wq; si[tid] = wi;
    __syncthreads();
    for (int s = 512; s > 0; s >>= 1) {
        if (tid < s) {
            float v2 = sv[tid + s]; int i2 = si[tid + s];
            if (v2 < sv[tid] || (v2 == sv[tid] && i2 < si[tid])) { sv[tid] = v2; si[tid] = i2; }
        }
        __syncthreads();
    }
    if (tid == 0) g_imin[g] = si[0];
}

// ---------------- bag = sum_i tAA_i * tmid[idx_i] ---------------------------
#define BPG 64
__global__ void bag_kernel(const int* __restrict__ idx) {
    const int g = blockIdx.y;
    const int blk = blockIdx.x;
    const int tid = threadIdx.x;  // 256
    const int CH = (GS + BPG - 1) / BPG;
    int i0 = blk * CH;
    int i1 = i0 + CH; if (i1 > GS) i1 = GS;
    float a0 = 0.f, a1 = 0.f;
    for (int i = i0; i < i1; i++) {
        int j = idx[g * GS + i];
        float w = g_tAA[g * GS + i];
        size_t base = (size_t)j * DD;
        a0 = fmaf(w, __half2float(g_th[base + tid]), a0);
        a1 = fmaf(w, __half2float(g_th[base + tid + 256]), a1);
    }
    atomicAdd(&g_bag[g * DD + tid], a0);
    atomicAdd(&g_bag[g * DD + tid + 256], a1);
}

// ---------------- final: preds + pseudo feats --------------------------------
__global__ void final_kernel(const float* __restrict__ Wc, const float* __restrict__ bc,
                             float* __restrict__ out) {
    const int tid = threadIdx.x;  // 512
    const int w = tid >> 5, lane = tid & 31;
    if (w < 16) {
        int g = w >> 1, c = w & 1;
        float s = 0.f;
        for (int k = lane; k < DD; k += 32)
            s = fmaf(g_bag[g * DD + k], Wc[k * 2 + c], s);
#pragma unroll
        for (int o = 16; o > 0; o >>= 1) s += __shfl_down_sync(0xFFFFFFFFu, s, o);
        if (lane == 0) out[g * 2 + c] = s + bc[c];
    }
    for (int e = tid; e < NG * 2 * DD; e += 512) {
        int g = e / (2 * DD);
        int r = (e / DD) & 1;
        int c = e % DD;
        int rowi = r ? g_imin[g] : g_imax[g];
        out[16 + e] = __half2float(g_th[(size_t)rowi * DD + c]);
    }
}

// ---------------- launch ------------------------------------------------------
extern "C" void kernel_launch(void* const* d_in, const int* in_sizes, int n_in,
                              void* d_out, int out_size) {
    const float* x    = (const float*)d_in[0];
    const int*   idx  = (const int*)d_in[1];
    const float* W1   = (const float*)d_in[2];
    const float* V    = (const float*)d_in[3];
    const float* watt = (const float*)d_in[4];
    const float* Wc   = (const float*)d_in[5];
    const float* bc   = (const float*)d_in[6];
    float* out = (float*)d_out;

    cudaFuncSetAttribute(gemm_mma<DIN, 0>,
                         cudaFuncAttributeMaxDynamicSharedMemorySize, SMEM_BYTES);
    cudaFuncSetAttribute(gemm_mma<DD, 1>,
                         cudaFuncAttributeMaxDynamicSharedMemorySize, SMEM_BYTES);

    prep_kernel<<<2048, 256>>>(x, W1, V);
    gemm_mma<DIN, 0><<<dim3(MTILES, NSLICES), NTHREADS, SMEM_BYTES>>>(watt, Wc);
    gemm_mma<DD, 1><<<dim3(MTILES, NSLICES), NTHREADS, SMEM_BYTES>>>(watt, Wc);
    combine_kernel<<<(NROWS + 255) / 256, 256>>>();
    group_kernel<<<NG, 1024>>>(idx);
    bag_kernel<<<dim3(BPG, NG), 256>>>(idx);
    final_kernel<<<1, 512>>>(Wc, bc, out);
}

// round 14
// speedup vs baseline: 1.0940x; 1.0408x over previous
#include <cuda_runtime.h>
#include <cuda_fp16.h>
#include <mma.h>
#include <cstdint>

using namespace nvcuda;

// Problem constants
#define NROWS 100000
#define DIN   1024
#define DD    512
#define NG    8
#define GS    12500

// GEMM tiling: BK=64, 3-stage cp.async ring
#define BM 128
#define BN 128
#define BK 64
#define NTHREADS 256
#define STAGES 3
#define LDA 72       // A stride in halfs (144B): 64 data + 8 pad
#define LDB 136      // B stride in halfs (272B): 128 data + 8 pad
#define LDCS 68      // epilogue staging stride (fp32)
#define A_BYTES (BM * LDA * 2)            // 18432
#define B_BYTES (BK * LDB * 2)            // 17408
#define BUFB (A_BYTES + B_BYTES)          // 35840
#define SMEM_BYTES (STAGES * BUFB)        // 107520 (needs attr; 2 CTA/SM = 210KB < 228KB)
#define MTILES ((NROWS + BM - 1) / BM)    // 782
#define NSLICES (DD / BN)                 // 4

// ---------------- scratch (device globals; no allocation allowed) ----------
__device__ __half g_xh[(size_t)NROWS * DIN];   // 200 MB
__device__ __half g_th[(size_t)NROWS * DD];    // 100 MB (tmid, fp16)
__device__ __half g_W1h[DIN * DD];
__device__ __half g_Vh[DD * DD];
__device__ float    g_escore[NROWS];           // exp(scores)
__device__ float    g_d[NROWS];
__device__ float    g_spart[NSLICES * NROWS];
__device__ float    g_dpart[NSLICES * NROWS];
__device__ float    g_tAA[NG * GS];
__device__ float    g_bag[NG * DD];
__device__ float    g_Z;
__device__ int      g_imax[NG];
__device__ int      g_imin[NG];

// ---------------- helpers ---------------------------------------------------
__device__ __forceinline__ float tanh_fast(float x) {
    float y;
    asm("tanh.approx.f32 %0, %1;" : "=f"(y) : "f"(x));
    return y;
}
__device__ __forceinline__ void cp_async16(uint32_t dst, const void* src, bool pred) {
    int sz = pred ? 16 : 0;
    asm volatile("cp.async.cg.shared.global [%0], [%1], 16, %2;\n"
                 :: "r"(dst), "l"(src), "r"(sz));
}
__device__ __forceinline__ void cp_commit() {
    asm volatile("cp.async.commit_group;\n" ::: "memory");
}
template <int N>
__device__ __forceinline__ void cp_wait() {
    asm volatile("cp.async.wait_group %0;\n" :: "n"(N) : "memory");
}

// ---------------- prep: convert x, W1, V to fp16 ----------------------------
__global__ void prep_kernel(const float* __restrict__ x, const float* __restrict__ W1,
                            const float* __restrict__ V) {
    int t = blockIdx.x * blockDim.x + threadIdx.x;
    int stride = gridDim.x * blockDim.x;
    for (int i = t; i < NROWS * DIN / 4; i += stride) {
        float4 v = ((const float4*)x)[i];
        __half h[4] = {__float2half(v.x), __float2half(v.y),
                       __float2half(v.z), __float2half(v.w)};
        ((uint2*)g_xh)[i] = *(uint2*)h;
    }
    for (int i = t; i < DIN * DD / 4; i += stride) {
        float4 v = ((const float4*)W1)[i];
        __half h[4] = {__float2half(v.x), __float2half(v.y),
                       __float2half(v.z), __float2half(v.w)};
        ((uint2*)g_W1h)[i] = *(uint2*)h;
    }
    for (int i = t; i < DD * DD / 4; i += stride) {
        float4 v = ((const float4*)V)[i];
        __half h[4] = {__float2half(v.x), __float2half(v.y),
                       __float2half(v.z), __float2half(v.w)};
        ((uint2*)g_Vh)[i] = *(uint2*)h;
    }
    if (t < NG * DD) g_bag[t] = 0.f;
    if (t == 0) g_Z = 0.f;
}

// ---------------- fp16 WMMA GEMM, BK=64, 3-stage cp.async -------------------
// MODE 0: C = x @ W1 (K=1024); epilogue: relu -> g_th (fp16), dpart = relu(C).(Wc1-Wc0)
// MODE 1: C = tmid @ V (K=512); epilogue: spart = sum_n tanh(C[.,n]) * watt[n]
template <int KTOT, int MODE>
__global__ void __launch_bounds__(NTHREADS, 2)
gemm_mma(const float* __restrict__ watt, const float* __restrict__ Wc) {
    extern __shared__ char dsm[];
    const __half* Ag = (MODE == 0) ? g_xh : g_th;
    const __half* Bg = (MODE == 0) ? g_W1h : g_Vh;

    const int tid = threadIdx.x;
    const int wid = tid >> 5;
    const int m0 = blockIdx.x * BM;
    const int n0 = blockIdx.y * BN;

    const int wm = (wid >> 1) * 32;
    const int wn = (wid & 1) * 64;

    wmma::fragment<wmma::accumulator, 16, 16, 16, float> acc[2][4];
#pragma unroll
    for (int i = 0; i < 2; i++)
#pragma unroll
        for (int n = 0; n < 4; n++) wmma::fill_fragment(acc[i][n], 0.f);

    // cp.async maps.
    // A tile 128x64 halfs = 1024 x 16B chunks (8/row); thread does 4 chunks.
    //   chunk ch: row = ch>>3, kq = ch&7 -> dst row*144 + kq*16
    // B tile 64x128 halfs = 1024 x 16B chunks (16/row); thread does 4 chunks.
    //   chunk ch: row = ch>>4, col = ch&15 -> dst row*272 + col*16
    const uint32_t sb0 = (uint32_t)__cvta_generic_to_shared(dsm);

    auto issue = [&](int kcs) {
        const uint32_t sb = sb0 + (kcs % STAGES) * BUFB;
#pragma unroll
        for (int p = 0; p < 4; p++) {
            int ch = tid + p * 256;
            int row = ch >> 3, kq = ch & 7;
            bool av = (m0 + row) < NROWS;
            int gr = av ? (m0 + row) : (NROWS - 1);
            cp_async16(sb + row * 144 + kq * 16,
                       Ag + (size_t)gr * KTOT + kcs * BK + kq * 8, av);
        }
#pragma unroll
        for (int p = 0; p < 4; p++) {
            int ch = tid + p * 256;
            int row = ch >> 4, col = ch & 15;
            cp_async16(sb + A_BYTES + row * 272 + col * 16,
                       Bg + (size_t)(kcs * BK + row) * DD + n0 + col * 8, true);
        }
        cp_commit();
    };

    const int KC = KTOT / BK;   // 16 (MODE 0) / 8 (MODE 1)
#pragma unroll
    for (int s = 0; s < STAGES - 1; s++) issue(s);

    for (int kc = 0; kc < KC; kc++) {
        cp_wait<STAGES - 2>();
        __syncthreads();
        if (kc + STAGES - 1 < KC) issue(kc + STAGES - 1);

        char* buf = dsm + (kc % STAGES) * BUFB;
        __half* As = (__half*)buf;
        __half* Bs = (__half*)(buf + A_BYTES);

#pragma unroll
        for (int ks = 0; ks < 4; ks++) {
            wmma::fragment<wmma::matrix_a, 16, 16, 16, __half, wmma::row_major> fa[2];
#pragma unroll
            for (int i = 0; i < 2; i++)
                wmma::load_matrix_sync(fa[i], &As[(wm + 16 * i) * LDA + ks * 16], LDA);
#pragma unroll
            for (int n = 0; n < 4; n++) {
                wmma::fragment<wmma::matrix_b, 16, 16, 16, __half, wmma::row_major> fb;
                wmma::load_matrix_sync(fb, &Bs[ks * 16 * LDB + wn + 16 * n], LDB);
#pragma unroll
                for (int i = 0; i < 2; i++)
                    wmma::mma_sync(acc[i][n], fa[i], fb, acc[i][n]);
            }
        }
        __syncthreads();
    }
    cp_wait<0>();
    __syncthreads();

    // ---------------- epilogue: stage C in two 64-col halves ----------------
    float* Cs = (float*)dsm;   // 34816 B < SMEM_BYTES
    const int row = tid >> 1;
    const int q = tid & 1;
    const int grow = m0 + row;
    float racc = 0.f;

#pragma unroll
    for (int hn = 0; hn < 2; hn++) {
        __syncthreads();
        if ((wid & 1) == hn) {
#pragma unroll
            for (int i = 0; i < 2; i++)
#pragma unroll
                for (int n = 0; n < 4; n++)
                    wmma::store_matrix_sync(&Cs[(wm + 16 * i) * LDCS + 16 * n],
                                            acc[i][n], LDCS, wmma::mem_row_major);
        }
        __syncthreads();
        if (grow < NROWS) {
            const int cbase = n0 + hn * 64 + q * 32;
            if (MODE == 0) {
#pragma unroll
                for (int j = 0; j < 32; j += 4) {
                    float4 v = *(float4*)&Cs[row * LDCS + q * 32 + j];
                    float vv[4] = {fmaxf(v.x, 0.f), fmaxf(v.y, 0.f),
                                   fmaxf(v.z, 0.f), fmaxf(v.w, 0.f)};
                    __half h[4];
                    int c = cbase + j;
#pragma unroll
                    for (int e = 0; e < 4; e++) {
                        h[e] = __float2half(vv[e]);
                        racc = fmaf(vv[e], Wc[2 * (c + e) + 1] - Wc[2 * (c + e)], racc);
                    }
                    *(uint2*)&g_th[(size_t)grow * DD + c] = *(uint2*)h;
                }
            } else {
#pragma unroll
                for (int j = 0; j < 32; j++) {
                    float y = Cs[row * LDCS + q * 32 + j];
                    racc = fmaf(tanh_fast(y), watt[cbase + j], racc);
                }
            }
        }
    }
    racc += __shfl_xor_sync(0xFFFFFFFFu, racc, 1);
    if (q == 0 && grow < NROWS) {
        if (MODE == 0)
            g_dpart[(size_t)blockIdx.y * NROWS + grow] = racc;
        else
            g_spart[(size_t)blockIdx.y * NROWS + grow] = racc;
    }
}

// ---------------- combine partials + exp + global Z --------------------------
__global__ void combine_kernel() {
    __shared__ float sm[256];
    int i = blockIdx.x * blockDim.x + threadIdx.x;
    float e = 0.f;
    if (i < NROWS) {
        g_d[i] = (g_dpart[i] + g_dpart[NROWS + i]) +
                 (g_dpart[2 * NROWS + i] + g_dpart[3 * NROWS + i]);
        float s = (g_spart[i] + g_spart[NROWS + i]) +
                  (g_spart[2 * NROWS + i] + g_spart[3 * NROWS + i]);
        e = expf(s);
        g_escore[i] = e;
    }
    sm[threadIdx.x] = e;
    __syncthreads();
    for (int o = 128; o > 0; o >>= 1) {
        if (threadIdx.x < o) sm[threadIdx.x] += sm[threadIdx.x + o];
        __syncthreads();
    }
    if (threadIdx.x == 0) atomicAdd(&g_Z, sm[0]);
}

// ---------------- per-group re-softmax + argmax/argmin ----------------------
#define GITER 13  // ceil(12500/1024)
__global__ __launch_bounds__(1024, 1)
void group_kernel(const int* __restrict__ idx) {
    __shared__ float sv[1024];
    __shared__ int si[1024];
    const int g = blockIdx.x;
    const int tid = threadIdx.x;
    const float invZ = 1.f / g_Z;

    float ex[GITER];
    int js[GITER];
    float lsum = 0.f;
#pragma unroll
    for (int t = 0; t < GITER; t++) {
        int i = tid + t * 1024;
        if (i < GS) {
            int j = idx[g * GS + i];
            float a = g_escore[j] * invZ;   // AA[j] in (0,1)
            ex[t] = expf(a);
            js[t] = j;
            lsum += ex[t];
        } else {
            ex[t] = 0.f;
            js[t] = 0;
        }
    }
    sv[tid] = lsum;
    __syncthreads();
    for (int s = 512; s > 0; s >>= 1) {
        if (tid < s) sv[tid] += sv[tid + s];
        __syncthreads();
    }
    const float invS = 1.f / sv[0];
    __syncthreads();

    float bq = -1e30f; int bi = GS;
    float wq =  1e30f; int wi = GS;
#pragma unroll
    for (int t = 0; t < GITER; t++) {
        int i = tid + t * 1024;
        if (i < GS) {
            float ta = ex[t] * invS;
            g_tAA[g * GS + i] = ta;
            float qv = ta * g_d[js[t]];
            if (qv > bq || (qv == bq && i < bi)) { bq = qv; bi = i; }
            if (qv < wq || (qv == wq && i < wi)) { wq = qv; wi = i; }
        }
    }
    sv[tid] = bq; si[tid] = bi;
    __syncthreads();
    for (int s = 512; s > 0; s >>= 1) {
        if (tid < s) {
            float v2 = sv[tid + s]; int i2 = si[tid + s];
            if (v2 > sv[tid] || (v2 == sv[tid] && i2 < si[tid])) { sv[tid] = v2; si[tid] = i2; }
        }
        __syncthreads();
    }
    if (tid == 0) g_imax[g] = si[0];
    __syncthreads();
    sv[tid] = wq; si[tid] = wi;
    __syncthreads();
    for (int s = 512; s > 0; s >>= 1) {
        if (tid < s) {
            float v2 = sv[tid + s]; int i2 = si[tid + s];
            if (v2 < sv[tid] || (v2 == sv[tid] && i2 < si[tid])) { sv[tid] = v2; si[tid] = i2; }
        }
        __syncthreads();
    }
    if (tid == 0) g_imin[g] = si[0];
}

// ---------------- bag = sum_i tAA_i * tmid[idx_i] ---------------------------
#define BPG 64
__global__ void bag_kernel(const int* __restrict__ idx) {
    const int g = blockIdx.y;
    const int blk = blockIdx.x;
    const int tid = threadIdx.x;  // 256
    const int CH = (GS + BPG - 1) / BPG;
    int i0 = blk * CH;
    int i1 = i0 + CH; if (i1 > GS) i1 = GS;
    float a0 = 0.f, a1 = 0.f;
    for (int i = i0; i < i1; i++) {
        int j = idx[g * GS + i];
        float w = g_tAA[g * GS + i];
        size_t base = (size_t)j * DD;
        a0 = fmaf(w, __half2float(g_th[base + tid]), a0);
        a1 = fmaf(w, __half2float(g_th[base + tid + 256]), a1);
    }
    atomicAdd(&g_bag[g * DD + tid], a0);
    atomicAdd(&g_bag[g * DD + tid + 256], a1);
}

// ---------------- final: preds + pseudo feats --------------------------------
__global__ void final_kernel(const float* __restrict__ Wc, const float* __restrict__ bc,
                             float* __restrict__ out) {
    const int tid = threadIdx.x;  // 512
    const int w = tid >> 5, lane = tid & 31;
    if (w < 16) {
        int g = w >> 1, c = w & 1;
        float s = 0.f;
        for (int k = lane; k < DD; k += 32)
            s = fmaf(g_bag[g * DD + k], Wc[k * 2 + c], s);
#pragma unroll
        for (int o = 16; o > 0; o >>= 1) s += __shfl_down_sync(0xFFFFFFFFu, s, o);
        if (lane == 0) out[g * 2 + c] = s + bc[c];
    }
    for (int e = tid; e < NG * 2 * DD; e += 512) {
        int g = e / (2 * DD);
        int r = (e / DD) & 1;
        int c = e % DD;
        int rowi = r ? g_imin[g] : g_imax[g];
        out[16 + e] = __half2float(g_th[(size_t)rowi * DD + c]);
    }
}

// ---------------- launch ------------------------------------------------------
extern "C" void kernel_launch(void* const* d_in, const int* in_sizes, int n_in,
                              void* d_out, int out_size) {
    const float* x    = (const float*)d_in[0];
    const int*   idx  = (const int*)d_in[1];
    const float* W1   = (const float*)d_in[2];
    const float* V    = (const float*)d_in[3];
    const float* watt = (const float*)d_in[4];
    const float* Wc   = (const float*)d_in[5];
    const float* bc   = (const float*)d_in[6];
    float* out = (float*)d_out;

    cudaFuncSetAttribute(gemm_mma<DIN, 0>,
                         cudaFuncAttributeMaxDynamicSharedMemorySize, SMEM_BYTES);
    cudaFuncSetAttribute(gemm_mma<DD, 1>,
                         cudaFuncAttributeMaxDynamicSharedMemorySize, SMEM_BYTES);

    prep_kernel<<<2048, 256>>>(x, W1, V);
    gemm_mma<DIN, 0><<<dim3(MTILES, NSLICES), NTHREADS, SMEM_BYTES>>>(watt, Wc);
    gemm_mma<DD, 1><<<dim3(MTILES, NSLICES), NTHREADS, SMEM_BYTES>>>(watt, Wc);
    combine_kernel<<<(NROWS + 255) / 256, 256>>>();
    group_kernel<<<NG, 1024>>>(idx);
    bag_kernel<<<dim3(BPG, NG), 256>>>(idx);
    final_kernel<<<1, 512>>>(Wc, bc, out);
}